// round 3
// baseline (speedup 1.0000x reference)
#include <cuda_runtime.h>

#define NB 2
#define AB 1344
#define LB 96
#define ATOMS 14
#define DB 128
#define HB 8
#define DEPTH 3
#define RB (NB*AB)      /* 2688 rows */
#define EB (HB*DB)      /* 1024 cols */
#define WORDS (AB/32)   /* 42 */

// ---------------- scratch (device globals; no allocation allowed) ----------------
__device__ float g_fp[RB*EB];          // projected features (N,A,H,D)  ~11MB
__device__ float g_x0[RB*DB];          // ping
__device__ float g_x1[RB*DB];          // pong
__device__ float g_src[NB*HB*AB];
__device__ float g_tag[NB*HB*AB];
__device__ float g_es [NB*HB*AB];      // exp(src)
__device__ float g_es2[NB*HB*AB];      // exp(0.2*src)
__device__ float g_P  [NB*HB*AB];      // exp(tag)
__device__ float g_Q  [NB*HB*AB];      // exp(0.2*tag)
__device__ float g_diag[NB*HB*AB];
__device__ unsigned g_ebits[NB*AB*WORDS];

// ---------------- pack edge_mask (int32 0/1 words) -> bits ----------------
__global__ void pack_edges_k(const unsigned int* __restrict__ em) {
    int w = blockIdx.x * 8 + (threadIdx.x >> 5);
    int lane = threadIdx.x & 31;
    unsigned int v = em[(size_t)w * 32 + lane];
    unsigned m = __ballot_sync(0xffffffffu, v != 0u);
    if (lane == 0) g_ebits[w] = m;
}

// ---------------- GEMM: fp = X (2688x128) * W^T (1024x128), masked ----------------
// block tile 64x128, K-tile 32, 256 threads, thread tile 4x8
__global__ void gemm_fp_k(const float* __restrict__ X, const float* __restrict__ W,
                          const int* __restrict__ mask) {
    __shared__ float As[32][68];    // [k][row], padded
    __shared__ float Bs[32][132];   // [k][col]
    int tid = threadIdx.x;
    int tx = tid & 15, ty = tid >> 4;
    int rowBase = blockIdx.x * 64;
    int colBase = blockIdx.y * 128;

    float acc[4][8];
#pragma unroll
    for (int i = 0; i < 4; i++)
#pragma unroll
        for (int j = 0; j < 8; j++) acc[i][j] = 0.f;

    for (int k0 = 0; k0 < 128; k0 += 32) {
#pragma unroll
        for (int i = 0; i < 8; i++) {
            int e = tid + i * 256;          // 2048 elements
            int r = e >> 5, k = e & 31;
            As[k][r] = X[(rowBase + r) * 128 + k0 + k];
        }
#pragma unroll
        for (int i = 0; i < 16; i++) {
            int e = tid + i * 256;          // 4096 elements
            int c = e >> 5, k = e & 31;
            Bs[k][c] = W[(colBase + c) * 128 + k0 + k];
        }
        __syncthreads();
#pragma unroll
        for (int kk = 0; kk < 32; kk++) {
            float4 a4 = *(const float4*)&As[kk][ty * 4];
            float4 b0 = *(const float4*)&Bs[kk][tx * 8];
            float4 b1 = *(const float4*)&Bs[kk][tx * 8 + 4];
            float a[4] = {a4.x, a4.y, a4.z, a4.w};
            float b[8] = {b0.x, b0.y, b0.z, b0.w, b1.x, b1.y, b1.z, b1.w};
#pragma unroll
            for (int i = 0; i < 4; i++)
#pragma unroll
                for (int j = 0; j < 8; j++) acc[i][j] += a[i] * b[j];
        }
        __syncthreads();
    }
#pragma unroll
    for (int i = 0; i < 4; i++) {
        int r = rowBase + ty * 4 + i;
        float m = (mask[r] != 0) ? 1.f : 0.f;
        float4 v0 = make_float4(acc[i][0]*m, acc[i][1]*m, acc[i][2]*m, acc[i][3]*m);
        float4 v1 = make_float4(acc[i][4]*m, acc[i][5]*m, acc[i][6]*m, acc[i][7]*m);
        float* dst = &g_fp[(size_t)r * EB + colBase + tx * 8];
        *(float4*)dst = v0;
        *(float4*)(dst + 4) = v1;
    }
}

// ---------------- src/tag scores + exps ----------------
// block per (n,a), 8 warps = 8 heads
__global__ void scores_k(const float* __restrict__ ssrc, const float* __restrict__ stag) {
    int b = blockIdx.x;                  // row = n*AB + a
    int n = b / AB, a = b % AB;
    int wid = threadIdx.x >> 5, lane = threadIdx.x & 31;
    const float* fprow = &g_fp[(size_t)b * EB + wid * DB];
    const float* ws = &ssrc[wid * DB];
    const float* wt = &stag[wid * DB];
    float ps = 0.f, pt = 0.f;
#pragma unroll
    for (int i = 0; i < 4; i++) {
        float v = fprow[lane + i * 32];
        ps += v * ws[lane + i * 32];
        pt += v * wt[lane + i * 32];
    }
#pragma unroll
    for (int o = 16; o; o >>= 1) {
        ps += __shfl_xor_sync(0xffffffffu, ps, o);
        pt += __shfl_xor_sync(0xffffffffu, pt, o);
    }
    if (lane == 0) {
        int idx = (n * HB + wid) * AB + a;
        g_src[idx] = ps;
        g_tag[idx] = pt;
        g_es [idx] = __expf(ps);
        g_es2[idx] = __expf(0.2f * ps);
        g_P  [idx] = __expf(pt);
        g_Q  [idx] = __expf(0.2f * pt);
    }
}

// ---------------- diagonal attention coefficient ----------------
// grid: N*H*(A/16), 256 threads (8 warps, each warp handles 2 rows)
#define ATILE 16
__global__ void attn_k() {
    __shared__ float sT[AB], sP[AB], sQ[AB];
    __shared__ unsigned sE[ATILE][WORDS];
    int b = blockIdx.x;
    int atile = b % (AB / ATILE);
    int nh = b / (AB / ATILE);
    int h = nh % HB, n = nh / HB;
    int tid = threadIdx.x;
    int base = (n * HB + h) * AB;
    for (int j = tid; j < AB; j += 256) {
        sT[j] = g_tag[base + j];
        sP[j] = g_P[base + j];
        sQ[j] = g_Q[base + j];
    }
    int a0 = atile * ATILE;
    for (int w = tid; w < ATILE * WORDS; w += 256) {
        int rr = w / WORDS, ww = w % WORDS;
        sE[rr][ww] = g_ebits[(n * AB + a0 + rr) * WORDS + ww];
    }
    __syncthreads();
    int wid = tid >> 5, lane = tid & 31;
    unsigned lmask = 1u << lane;
#pragma unroll
    for (int rr = wid; rr < ATILE; rr += 8) {
        int a = a0 + rr;
        float s = g_src[base + a];
        float ns = -s;
        float sumP = 0.f, sumQ = 0.f;
#pragma unroll 6
        for (int it = 0; it < WORDS; it++) {
            unsigned wbits = sE[rr][it];
            int j = it * 32 + lane;
            float t = sT[j];
            if (wbits & lmask) {
                if (t > ns) sumP += sP[j];
                else        sumQ += sQ[j];
            }
        }
#pragma unroll
        for (int o = 16; o; o >>= 1) {
            sumP += __shfl_xor_sync(0xffffffffu, sumP, o);
            sumQ += __shfl_xor_sync(0xffffffffu, sumQ, o);
        }
        if (lane == 0) {
            float es = g_es[base + a], es2 = g_es2[base + a];
            float S = es * sumP + es2 * sumQ;
            unsigned selfb = sE[rr][a >> 5] & (1u << (a & 31));
            float num = 0.f;
            if (selfb) {
                float t = sT[a];
                num = (s + t > 0.f) ? es * sP[a] : es2 * sQ[a];
            }
            g_diag[base + a] = num / S;
        }
    }
}

// ---------------- epilogue: fo = diag*fp -> LN -> +skip -> head mean -> +bias ----------------
__device__ __forceinline__ float blockSum128(float v, float* red) {
#pragma unroll
    for (int o = 16; o; o >>= 1) v += __shfl_xor_sync(0xffffffffu, v, o);
    int wid = threadIdx.x >> 5, lane = threadIdx.x & 31;
    __syncthreads();
    if (lane == 0) red[wid] = v;
    __syncthreads();
    return red[0] + red[1] + red[2] + red[3];
}

__global__ void epi_k(const float* __restrict__ xin, float* __restrict__ xout,
                      const float* __restrict__ lng, const float* __restrict__ lnb,
                      const float* __restrict__ bias) {
    __shared__ float red[4];
    int b = blockIdx.x;                  // n*AB + a
    int n = b / AB, a = b % AB;
    int d = threadIdx.x;                 // 128 threads
    const float* fpb = &g_fp[(size_t)b * EB];
    float gd = lng[d], bd = lnb[d];
    float acc = 0.f;
#pragma unroll
    for (int h = 0; h < HB; h++) {
        float dg = g_diag[(n * HB + h) * AB + a];
        float v = dg * fpb[h * DB + d];
        float mu = blockSum128(v, red) * (1.f / 128.f);
        float dv = v - mu;
        float var = blockSum128(dv * dv, red) * (1.f / 128.f);
        float rstd = rsqrtf(var + 1e-5f);
        acc += dv * rstd * gd + bd;
    }
    float fin = xin[(size_t)b * DB + d];
    xout[(size_t)b * DB + d] = acc * 0.125f + fin + bias[d];
}

// ---------------- readout: mask + sum 14 atoms per residue ----------------
__global__ void readout_k(const float* __restrict__ x, const int* __restrict__ mask,
                          float* __restrict__ out) {
    int b = blockIdx.x;                  // n*LB + l
    int n = b / LB, l = b % LB;
    int d = threadIdx.x;
    float s = 0.f;
#pragma unroll
    for (int t = 0; t < ATOMS; t++) {
        int a = l * ATOMS + t;
        if (mask[n * AB + a] != 0) s += x[(size_t)(n * AB + a) * DB + d];
    }
    out[(size_t)b * DB + d] = s;
}

// ---------------- launch ----------------
extern "C" void kernel_launch(void* const* d_in, const int* in_sizes, int n_in,
                              void* d_out, int out_size) {
    const float*        feats = (const float*)d_in[0];
    const int*          mask  = (const int*)d_in[1];
    const unsigned int* emask = (const unsigned int*)d_in[2];
    const float*        W     = (const float*)d_in[3];
    const float*        ssrc  = (const float*)d_in[4];
    const float*        stag  = (const float*)d_in[5];
    const float*        bias  = (const float*)d_in[6];
    const float*        lng   = (const float*)d_in[7];
    const float*        lnb   = (const float*)d_in[8];
    float* out = (float*)d_out;

    float *px0 = nullptr, *px1 = nullptr;
    cudaGetSymbolAddress((void**)&px0, g_x0);
    cudaGetSymbolAddress((void**)&px1, g_x1);

    pack_edges_k<<<(NB * AB * WORDS) / 8, 256>>>(emask);

    const float* xin = feats;
    float* bufs[2] = {px0, px1};
    for (int l = 0; l < DEPTH; l++) {
        float* xout = bufs[l & 1];
        gemm_fp_k<<<dim3(RB / 64, EB / 128), 256>>>(xin, W + (size_t)l * EB * DB, mask);
        scores_k<<<RB, 256>>>(ssrc + l * HB * DB, stag + l * HB * DB);
        attn_k<<<NB * HB * (AB / ATILE), 256>>>();
        epi_k<<<RB, 128>>>(xin, xout, lng + l * DB, lnb + l * DB, bias + l * DB);
        xin = xout;
    }
    readout_k<<<NB * LB, 128>>>(xin, mask, out);
}

// round 4
// speedup vs baseline: 1.2488x; 1.2488x over previous
#include <cuda_runtime.h>

#define NB 2
#define AB 1344
#define LB 96
#define ATOMS 14
#define DB 128
#define HB 8
#define DEPTH 3
#define RB (NB*AB)      /* 2688 rows */
#define EB (HB*DB)      /* 1024 cols */
#define WORDS (AB/32)   /* 42 */
#define ATILE 32

// ---------------- scratch ----------------
__device__ float  g_fp[RB*EB];          // projected features (N,A,H,D)
__device__ float  g_x0[RB*DB];
__device__ float  g_x1[RB*DB];
__device__ float  g_es [NB*HB*AB];      // exp(src)
__device__ float  g_es2[NB*HB*AB];      // exp(0.2*src)
__device__ float2 g_PQ [NB*HB*AB];      // (exp(tag), exp(0.2*tag))
__device__ float  g_diag[NB*HB*AB];
__device__ unsigned g_ebits[NB*AB*WORDS];

// ---------------- pack edge_mask (int32 words) -> bits ----------------
__global__ void pack_edges_k(const unsigned int* __restrict__ em) {
    int w = blockIdx.x * 8 + (threadIdx.x >> 5);
    int lane = threadIdx.x & 31;
    unsigned int v = em[(size_t)w * 32 + lane];
    unsigned m = __ballot_sync(0xffffffffu, v != 0u);
    if (lane == 0) g_ebits[w] = m;
}

// ---------------- GEMM + fused scores/exps ----------------
// block tile 64 rows x 128 cols (one head), 256 threads, thread tile 4x8
__global__ void gemm_fp_k(const float* __restrict__ X, const float* __restrict__ W,
                          const int* __restrict__ mask,
                          const float* __restrict__ ssrc, const float* __restrict__ stag) {
    __shared__ float As[32][68];
    __shared__ float Bs[32][132];
    __shared__ float sred[2][64][17];
    int tid = threadIdx.x;
    int tx = tid & 15, ty = tid >> 4;
    int rowBase = blockIdx.x * 64;
    int h = blockIdx.y;
    int colBase = h * 128;

    float acc[4][8];
#pragma unroll
    for (int i = 0; i < 4; i++)
#pragma unroll
        for (int j = 0; j < 8; j++) acc[i][j] = 0.f;

    for (int k0 = 0; k0 < 128; k0 += 32) {
#pragma unroll
        for (int i = 0; i < 8; i++) {
            int e = tid + i * 256;
            int r = e >> 5, k = e & 31;
            As[k][r] = X[(rowBase + r) * 128 + k0 + k];
        }
#pragma unroll
        for (int i = 0; i < 16; i++) {
            int e = tid + i * 256;
            int c = e >> 5, k = e & 31;
            Bs[k][c] = W[(colBase + c) * 128 + k0 + k];
        }
        __syncthreads();
#pragma unroll
        for (int kk = 0; kk < 32; kk++) {
            float4 a4 = *(const float4*)&As[kk][ty * 4];
            float4 b0 = *(const float4*)&Bs[kk][tx * 8];
            float4 b1 = *(const float4*)&Bs[kk][tx * 8 + 4];
            float a[4] = {a4.x, a4.y, a4.z, a4.w};
            float b[8] = {b0.x, b0.y, b0.z, b0.w, b1.x, b1.y, b1.z, b1.w};
#pragma unroll
            for (int i = 0; i < 4; i++)
#pragma unroll
                for (int j = 0; j < 8; j++) acc[i][j] += a[i] * b[j];
        }
        __syncthreads();
    }

    // per-thread column weights for src/tag dots
    float ws[8], wt[8];
#pragma unroll
    for (int j = 0; j < 8; j++) {
        ws[j] = ssrc[colBase + tx * 8 + j];
        wt[j] = stag[colBase + tx * 8 + j];
    }

#pragma unroll
    for (int i = 0; i < 4; i++) {
        int rl = ty * 4 + i;
        int r = rowBase + rl;
        float m = (mask[r] != 0) ? 1.f : 0.f;
        float ps = 0.f, pt = 0.f;
#pragma unroll
        for (int j = 0; j < 8; j++) {
            acc[i][j] *= m;
            ps += acc[i][j] * ws[j];
            pt += acc[i][j] * wt[j];
        }
        sred[0][rl][tx] = ps;
        sred[1][rl][tx] = pt;
        float4 v0 = make_float4(acc[i][0], acc[i][1], acc[i][2], acc[i][3]);
        float4 v1 = make_float4(acc[i][4], acc[i][5], acc[i][6], acc[i][7]);
        float* dst = &g_fp[(size_t)r * EB + colBase + tx * 8];
        *(float4*)dst = v0;
        *(float4*)(dst + 4) = v1;
    }
    __syncthreads();

    if (tid < 64) {
        int r = rowBase + tid;              // global row, same n within block (1344%64==0)
        int n = r / AB, a = r % AB;
        float ps = 0.f, pt = 0.f;
#pragma unroll
        for (int t = 0; t < 16; t++) {
            ps += sred[0][tid][t];
            pt += sred[1][tid][t];
        }
        int idx = (n * HB + h) * AB + a;
        g_es [idx] = __expf(ps);
        g_es2[idx] = __expf(0.2f * ps);
        g_PQ [idx] = make_float2(__expf(pt), __expf(0.2f * pt));
    }
}

// ---------------- diagonal attention coefficient ----------------
// grid: N*H*(A/ATILE), 256 threads; warp w owns rows [w*4, w*4+4), 2 rows per pass
__global__ void attn_k() {
    __shared__ float2 sPQ[AB];
    __shared__ unsigned sEw[ATILE * WORDS];
    __shared__ float sEs[ATILE], sEs2[ATILE], sInv[ATILE];
    int b = blockIdx.x;
    int atile = b % (AB / ATILE);
    int nh = b / (AB / ATILE);       // n*HB + h
    int n = nh / HB;
    int base = nh * AB;
    int tid = threadIdx.x;
    int a0 = atile * ATILE;

    for (int j = tid; j < AB; j += 256) sPQ[j] = g_PQ[base + j];
    for (int w = tid; w < ATILE * WORDS; w += 256)
        sEw[w] = g_ebits[(size_t)(n * AB + a0) * WORDS + w];
    if (tid < ATILE) {
        float es = g_es[base + a0 + tid];
        sEs[tid] = es;
        sEs2[tid] = g_es2[base + a0 + tid];
        sInv[tid] = 1.0f / es;       // threshold: P[j] > 1/es  <=>  tag_j > -src_a
    }
    __syncthreads();

    int wid = tid >> 5, lane = tid & 31;
#pragma unroll
    for (int p = 0; p < 2; p++) {
        int r0 = wid * 4 + p * 2;
        int r1 = r0 + 1;
        float inv0 = sInv[r0], inv1 = sInv[r1];
        const unsigned* e0 = &sEw[r0 * WORDS];
        const unsigned* e1 = &sEw[r1 * WORDS];
        float sp0 = 0.f, sq0 = 0.f, sp1 = 0.f, sq1 = 0.f;
#pragma unroll
        for (int it = 0; it < WORDS; it++) {
            float2 pq = sPQ[it * 32 + lane];
            unsigned w0 = e0[it], w1 = e1[it];
            bool c0 = (w0 >> lane) & 1u;
            bool c1 = (w1 >> lane) & 1u;
            bool hi0 = pq.x > inv0;
            bool hi1 = pq.x > inv1;
            if (c0) { if (hi0) sp0 += pq.x; else sq0 += pq.y; }
            if (c1) { if (hi1) sp1 += pq.x; else sq1 += pq.y; }
        }
#pragma unroll
        for (int o = 16; o; o >>= 1) {
            sp0 += __shfl_xor_sync(0xffffffffu, sp0, o);
            sq0 += __shfl_xor_sync(0xffffffffu, sq0, o);
            sp1 += __shfl_xor_sync(0xffffffffu, sp1, o);
            sq1 += __shfl_xor_sync(0xffffffffu, sq1, o);
        }
        if (lane < 2) {
            int r = r0 + lane;
            float sp = lane ? sp1 : sp0;
            float sq = lane ? sq1 : sq0;
            int a = a0 + r;
            float es = sEs[r], es2 = sEs2[r];
            float S = es * sp + es2 * sq;
            unsigned selfb = sEw[r * WORDS + (a >> 5)] & (1u << (a & 31));
            float num = 0.f;
            if (selfb) {
                float2 pqa = sPQ[a];
                num = (pqa.x > sInv[r]) ? es * pqa.x : es2 * pqa.y;
            }
            g_diag[base + a] = num / S;
        }
    }
}

// ---------------- epilogue: warp-per-head LN -> +skip -> head mean -> +bias ----------------
__global__ void epi_k(const float* __restrict__ xin, float* __restrict__ xout,
                      const float* __restrict__ lng, const float* __restrict__ lnb,
                      const float* __restrict__ bias) {
    __shared__ float sv[HB][132];
    int b = blockIdx.x;                  // n*AB + a
    int n = b / AB, a = b % AB;
    int tid = threadIdx.x;               // 256 threads = 8 warps
    int h = tid >> 5, lane = tid & 31;

    float dg = g_diag[(n * HB + h) * AB + a];
    const float* fpb = &g_fp[(size_t)b * EB + h * DB];
    float v[4];
    float sum = 0.f, ss = 0.f;
#pragma unroll
    for (int i = 0; i < 4; i++) {
        v[i] = dg * fpb[lane + i * 32];
        sum += v[i];
        ss += v[i] * v[i];
    }
#pragma unroll
    for (int o = 16; o; o >>= 1) {
        sum += __shfl_xor_sync(0xffffffffu, sum, o);
        ss  += __shfl_xor_sync(0xffffffffu, ss, o);
    }
    float mu = sum * (1.f / 128.f);
    float var = ss * (1.f / 128.f) - mu * mu;
    float rstd = rsqrtf(var + 1e-5f);
#pragma unroll
    for (int i = 0; i < 4; i++) {
        int d = lane + i * 32;
        sv[h][d] = (v[i] - mu) * rstd * lng[d] + lnb[d];
    }
    __syncthreads();
    if (tid < 128) {
        int d = tid;
        float acc = 0.f;
#pragma unroll
        for (int hh = 0; hh < HB; hh++) acc += sv[hh][d];
        float fin = xin[(size_t)b * DB + d];
        xout[(size_t)b * DB + d] = acc * 0.125f + fin + bias[d];
    }
}

// ---------------- readout: mask + sum 14 atoms per residue ----------------
__global__ void readout_k(const float* __restrict__ x, const int* __restrict__ mask,
                          float* __restrict__ out) {
    int b = blockIdx.x;                  // n*LB + l
    int n = b / LB, l = b % LB;
    int d = threadIdx.x;
    float s = 0.f;
#pragma unroll
    for (int t = 0; t < ATOMS; t++) {
        int a = l * ATOMS + t;
        if (mask[n * AB + a] != 0) s += x[(size_t)(n * AB + a) * DB + d];
    }
    out[(size_t)b * DB + d] = s;
}

// ---------------- launch ----------------
extern "C" void kernel_launch(void* const* d_in, const int* in_sizes, int n_in,
                              void* d_out, int out_size) {
    const float*        feats = (const float*)d_in[0];
    const int*          mask  = (const int*)d_in[1];
    const unsigned int* emask = (const unsigned int*)d_in[2];
    const float*        W     = (const float*)d_in[3];
    const float*        ssrc  = (const float*)d_in[4];
    const float*        stag  = (const float*)d_in[5];
    const float*        bias  = (const float*)d_in[6];
    const float*        lng   = (const float*)d_in[7];
    const float*        lnb   = (const float*)d_in[8];
    float* out = (float*)d_out;

    float *px0 = nullptr, *px1 = nullptr;
    cudaGetSymbolAddress((void**)&px0, g_x0);
    cudaGetSymbolAddress((void**)&px1, g_x1);

    pack_edges_k<<<(NB * AB * WORDS) / 8, 256>>>(emask);

    const float* xin = feats;
    float* bufs[2] = {px0, px1};
    for (int l = 0; l < DEPTH; l++) {
        float* xout = bufs[l & 1];
        gemm_fp_k<<<dim3(RB / 64, HB), 256>>>(xin, W + (size_t)l * EB * DB, mask,
                                              ssrc + l * HB * DB, stag + l * HB * DB);
        attn_k<<<NB * HB * (AB / ATILE), 256>>>();
        epi_k<<<RB, 256>>>(xin, xout, lng + l * DB, lnb + l * DB, bias + l * DB);
        xin = xout;
    }
    readout_k<<<NB * LB, 128>>>(xin, mask, out);
}

// round 5
// speedup vs baseline: 2.0966x; 1.6788x over previous
#include <cuda_runtime.h>
#include <cuda_bf16.h>

#define NB 2
#define AB 1344
#define LB 96
#define ATOMS 14
#define DB 128
#define HB 8
#define DEPTH 3
#define RB (NB*AB)      /* 2688 rows */
#define EB (HB*DB)      /* 1024 cols */
#define WORDS (AB/32)   /* 42 */
#define ATILE 32
#define LDSB 136        /* padded row length (bf16 elems) */

// ---------------- scratch ----------------
__device__ float  g_fp[RB*EB];
__device__ float  g_x0[RB*DB];
__device__ float  g_x1[RB*DB];
__device__ float  g_es [NB*HB*AB];
__device__ float  g_es2[NB*HB*AB];
__device__ float2 g_PQ [NB*HB*AB];
__device__ float  g_diag[NB*HB*AB];
__device__ unsigned g_ebits[NB*AB*WORDS];

#define LDSM4(r0,r1,r2,r3,addr) asm volatile( \
  "ldmatrix.sync.aligned.m8n8.x4.shared.b16 {%0,%1,%2,%3}, [%4];" \
  : "=r"(r0),"=r"(r1),"=r"(r2),"=r"(r3) : "r"(addr))

#define MMA_BF16(c,a0,a1,a2,a3,b0,b1) asm volatile( \
  "mma.sync.aligned.m16n8k16.row.col.f32.bf16.bf16.f32 " \
  "{%0,%1,%2,%3},{%4,%5,%6,%7},{%8,%9},{%0,%1,%2,%3};" \
  : "+f"(c[0]),"+f"(c[1]),"+f"(c[2]),"+f"(c[3]) \
  : "r"(a0),"r"(a1),"r"(a2),"r"(a3),"r"(b0),"r"(b1))

// ---------------- pack edge_mask (int32 words) -> bits ----------------
__global__ void pack_edges_k(const unsigned int* __restrict__ em) {
    int w = blockIdx.x * 8 + (threadIdx.x >> 5);
    int lane = threadIdx.x & 31;
    unsigned int v = em[(size_t)w * 32 + lane];
    unsigned m = __ballot_sync(0xffffffffu, v != 0u);
    if (lane == 0) g_ebits[w] = m;
}

// ---------------- TC GEMM (bf16 split) + fused scores/exps ----------------
// block: 64 rows x 128 cols (one head), 256 threads, warp grid 4x2 of 16x64 tiles
__global__ void gemm_fp_k(const float* __restrict__ X, const float* __restrict__ W,
                          const int* __restrict__ mask,
                          const float* __restrict__ ssrc, const float* __restrict__ stag) {
    extern __shared__ __nv_bfloat16 sm[];
    __nv_bfloat16* Ahi = sm;
    __nv_bfloat16* Alo = sm + 64 * LDSB;
    __nv_bfloat16* Bhi = sm + 2 * 64 * LDSB;
    __nv_bfloat16* Blo = sm + 2 * 64 * LDSB + 128 * LDSB;
    __shared__ float sws[128], swt[128];
    __shared__ float sredPs[2][64], sredPt[2][64];

    int tid = threadIdx.x;
    int rowBase = blockIdx.x * 64;
    int h = blockIdx.y;
    int colBase = h * DB;

    if (tid < 128) sws[tid] = ssrc[colBase + tid];
    else           swt[tid - 128] = stag[colBase + tid - 128];

    // ---- load + hi/lo convert A (64x128) ----
#pragma unroll
    for (int i = 0; i < 8; i++) {
        int idx = tid + i * 256;                 // 2048 float4s
        int r = idx >> 5, c = (idx & 31) * 4;
        float4 v = *(const float4*)&X[(size_t)(rowBase + r) * 128 + c];
        __nv_bfloat16 h0 = __float2bfloat16(v.x), h1 = __float2bfloat16(v.y);
        __nv_bfloat16 h2 = __float2bfloat16(v.z), h3 = __float2bfloat16(v.w);
        __nv_bfloat16 l0 = __float2bfloat16(v.x - __bfloat162float(h0));
        __nv_bfloat16 l1 = __float2bfloat16(v.y - __bfloat162float(h1));
        __nv_bfloat16 l2 = __float2bfloat16(v.z - __bfloat162float(h2));
        __nv_bfloat16 l3 = __float2bfloat16(v.w - __bfloat162float(h3));
        int o = r * LDSB + c;
        *(__nv_bfloat162*)&Ahi[o]   = __halves2bfloat162(h0, h1);
        *(__nv_bfloat162*)&Ahi[o+2] = __halves2bfloat162(h2, h3);
        *(__nv_bfloat162*)&Alo[o]   = __halves2bfloat162(l0, l1);
        *(__nv_bfloat162*)&Alo[o+2] = __halves2bfloat162(l2, l3);
    }
    // ---- load + hi/lo convert B = W rows [h*128, h*128+128) ----
#pragma unroll
    for (int i = 0; i < 16; i++) {
        int idx = tid + i * 256;                 // 4096 float4s
        int r = idx >> 5, c = (idx & 31) * 4;
        float4 v = *(const float4*)&W[(size_t)(h * 128 + r) * 128 + c];
        __nv_bfloat16 h0 = __float2bfloat16(v.x), h1 = __float2bfloat16(v.y);
        __nv_bfloat16 h2 = __float2bfloat16(v.z), h3 = __float2bfloat16(v.w);
        __nv_bfloat16 l0 = __float2bfloat16(v.x - __bfloat162float(h0));
        __nv_bfloat16 l1 = __float2bfloat16(v.y - __bfloat162float(h1));
        __nv_bfloat16 l2 = __float2bfloat16(v.z - __bfloat162float(h2));
        __nv_bfloat16 l3 = __float2bfloat16(v.w - __bfloat162float(h3));
        int o = r * LDSB + c;
        *(__nv_bfloat162*)&Bhi[o]   = __halves2bfloat162(h0, h1);
        *(__nv_bfloat162*)&Bhi[o+2] = __halves2bfloat162(h2, h3);
        *(__nv_bfloat162*)&Blo[o]   = __halves2bfloat162(l0, l1);
        *(__nv_bfloat162*)&Blo[o+2] = __halves2bfloat162(l2, l3);
    }
    __syncthreads();

    int wid = tid >> 5, lane = tid & 31;
    int warpRow = wid & 3, warpCol = wid >> 2;
    int g = lane >> 2, tig = lane & 3;

    unsigned aoff = ((warpRow * 16 + (lane & 15)) * LDSB + (lane >> 4) * 8) * 2;
    unsigned boff = ((warpCol * 64 + (lane & 7) + (lane >> 4) * 8) * LDSB
                     + ((lane >> 3) & 1) * 8) * 2;
    unsigned aHiB = (unsigned)__cvta_generic_to_shared(Ahi) + aoff;
    unsigned aLoB = (unsigned)__cvta_generic_to_shared(Alo) + aoff;
    unsigned bHiB = (unsigned)__cvta_generic_to_shared(Bhi) + boff;
    unsigned bLoB = (unsigned)__cvta_generic_to_shared(Blo) + boff;

    float c[8][4];
#pragma unroll
    for (int t = 0; t < 8; t++)
#pragma unroll
        for (int j = 0; j < 4; j++) c[t][j] = 0.f;

#pragma unroll
    for (int ks = 0; ks < 8; ks++) {
        unsigned kb = ks * 32;                   // 16 bf16 = 32 bytes
        unsigned a0, a1, a2, a3, e0, e1, e2, e3;
        LDSM4(a0, a1, a2, a3, aHiB + kb);
        LDSM4(e0, e1, e2, e3, aLoB + kb);
        unsigned bh[16], bl[16];
#pragma unroll
        for (int g4 = 0; g4 < 4; g4++) {
            unsigned off = g4 * 16 * LDSB * 2 + kb;
            LDSM4(bh[g4*4], bh[g4*4+1], bh[g4*4+2], bh[g4*4+3], bHiB + off);
            LDSM4(bl[g4*4], bl[g4*4+1], bl[g4*4+2], bl[g4*4+3], bLoB + off);
        }
#pragma unroll
        for (int t = 0; t < 8; t++) {
            int bi = (t >> 1) * 4 + (t & 1) * 2;
            MMA_BF16(c[t], a0, a1, a2, a3, bh[bi], bh[bi+1]);
            MMA_BF16(c[t], a0, a1, a2, a3, bl[bi], bl[bi+1]);
            MMA_BF16(c[t], e0, e1, e2, e3, bh[bi], bh[bi+1]);
        }
    }

    // ---- epilogue: mask, store g_fp, fused src/tag scores ----
    int rA = rowBase + warpRow * 16 + g;
    int rBp = rA + 8;
    float mA = (mask[rA]  != 0) ? 1.f : 0.f;
    float mB = (mask[rBp] != 0) ? 1.f : 0.f;
    float psA = 0.f, ptA = 0.f, psB = 0.f, ptB = 0.f;
#pragma unroll
    for (int t = 0; t < 8; t++) {
        int cl = warpCol * 64 + t * 8 + tig * 2;
        float w0s = sws[cl], w1s = sws[cl+1], w0t = swt[cl], w1t = swt[cl+1];
        float c0 = c[t][0] * mA, c1 = c[t][1] * mA;
        float c2 = c[t][2] * mB, c3 = c[t][3] * mB;
        psA += c0 * w0s + c1 * w1s;  ptA += c0 * w0t + c1 * w1t;
        psB += c2 * w0s + c3 * w1s;  ptB += c2 * w0t + c3 * w1t;
        *(float2*)&g_fp[(size_t)rA  * EB + colBase + cl] = make_float2(c0, c1);
        *(float2*)&g_fp[(size_t)rBp * EB + colBase + cl] = make_float2(c2, c3);
    }
#pragma unroll
    for (int o = 1; o <= 2; o <<= 1) {
        psA += __shfl_xor_sync(0xffffffffu, psA, o);
        ptA += __shfl_xor_sync(0xffffffffu, ptA, o);
        psB += __shfl_xor_sync(0xffffffffu, psB, o);
        ptB += __shfl_xor_sync(0xffffffffu, ptB, o);
    }
    if (tig == 0) {
        int rl = warpRow * 16 + g;
        sredPs[warpCol][rl]     = psA;  sredPt[warpCol][rl]     = ptA;
        sredPs[warpCol][rl + 8] = psB;  sredPt[warpCol][rl + 8] = ptB;
    }
    __syncthreads();
    if (tid < 64) {
        int r = rowBase + tid;
        int n = r / AB, a = r % AB;
        float ps = sredPs[0][tid] + sredPs[1][tid];
        float pt = sredPt[0][tid] + sredPt[1][tid];
        int idx = (n * HB + h) * AB + a;
        g_es [idx] = __expf(ps);
        g_es2[idx] = __expf(0.2f * ps);
        g_PQ [idx] = make_float2(__expf(pt), __expf(0.2f * pt));
    }
}

// ---------------- diagonal attention coefficient ----------------
__global__ void attn_k() {
    __shared__ float2 sPQ[AB];
    __shared__ unsigned sEw[ATILE * WORDS];
    __shared__ float sEs[ATILE], sEs2[ATILE], sInv[ATILE];
    int b = blockIdx.x;
    int atile = b % (AB / ATILE);
    int nh = b / (AB / ATILE);
    int n = nh / HB;
    int base = nh * AB;
    int tid = threadIdx.x;
    int a0 = atile * ATILE;

    for (int j = tid; j < AB; j += 256) sPQ[j] = g_PQ[base + j];
    for (int w = tid; w < ATILE * WORDS; w += 256)
        sEw[w] = g_ebits[(size_t)(n * AB + a0) * WORDS + w];
    if (tid < ATILE) {
        float es = g_es[base + a0 + tid];
        sEs[tid] = es;
        sEs2[tid] = g_es2[base + a0 + tid];
        sInv[tid] = 1.0f / es;
    }
    __syncthreads();

    int wid = tid >> 5, lane = tid & 31;
#pragma unroll
    for (int p = 0; p < 2; p++) {
        int r0 = wid * 4 + p * 2;
        int r1 = r0 + 1;
        float inv0 = sInv[r0], inv1 = sInv[r1];
        const unsigned* e0 = &sEw[r0 * WORDS];
        const unsigned* e1 = &sEw[r1 * WORDS];
        float sp0 = 0.f, sq0 = 0.f, sp1 = 0.f, sq1 = 0.f;
#pragma unroll
        for (int it = 0; it < WORDS; it++) {
            float2 pq = sPQ[it * 32 + lane];
            unsigned w0 = e0[it], w1 = e1[it];
            bool c0 = (w0 >> lane) & 1u;
            bool c1 = (w1 >> lane) & 1u;
            if (c0) { if (pq.x > inv0) sp0 += pq.x; else sq0 += pq.y; }
            if (c1) { if (pq.x > inv1) sp1 += pq.x; else sq1 += pq.y; }
        }
#pragma unroll
        for (int o = 16; o; o >>= 1) {
            sp0 += __shfl_xor_sync(0xffffffffu, sp0, o);
            sq0 += __shfl_xor_sync(0xffffffffu, sq0, o);
            sp1 += __shfl_xor_sync(0xffffffffu, sp1, o);
            sq1 += __shfl_xor_sync(0xffffffffu, sq1, o);
        }
        if (lane < 2) {
            int r = r0 + lane;
            float sp = lane ? sp1 : sp0;
            float sq = lane ? sq1 : sq0;
            int a = a0 + r;
            float es = sEs[r], es2 = sEs2[r];
            float S = es * sp + es2 * sq;
            unsigned selfb = sEw[r * WORDS + (a >> 5)] & (1u << (a & 31));
            float num = 0.f;
            if (selfb) {
                float2 pqa = sPQ[a];
                num = (pqa.x > sInv[r]) ? es * pqa.x : es2 * pqa.y;
            }
            g_diag[base + a] = num / S;
        }
    }
}

// ---------------- epilogue: warp-per-head LN -> +skip -> head mean -> +bias ----------------
__global__ void epi_k(const float* __restrict__ xin, float* __restrict__ xout,
                      const float* __restrict__ lng, const float* __restrict__ lnb,
                      const float* __restrict__ bias) {
    __shared__ float sv[HB][132];
    int b = blockIdx.x;
    int n = b / AB, a = b % AB;
    int tid = threadIdx.x;
    int h = tid >> 5, lane = tid & 31;

    float dg = g_diag[(n * HB + h) * AB + a];
    const float* fpb = &g_fp[(size_t)b * EB + h * DB];
    float v[4];
    float sum = 0.f, ss = 0.f;
#pragma unroll
    for (int i = 0; i < 4; i++) {
        v[i] = dg * fpb[lane + i * 32];
        sum += v[i];
        ss += v[i] * v[i];
    }
#pragma unroll
    for (int o = 16; o; o >>= 1) {
        sum += __shfl_xor_sync(0xffffffffu, sum, o);
        ss  += __shfl_xor_sync(0xffffffffu, ss, o);
    }
    float mu = sum * (1.f / 128.f);
    float var = ss * (1.f / 128.f) - mu * mu;
    float rstd = rsqrtf(var + 1e-5f);
#pragma unroll
    for (int i = 0; i < 4; i++) {
        int d = lane + i * 32;
        sv[h][d] = (v[i] - mu) * rstd * lng[d] + lnb[d];
    }
    __syncthreads();
    if (tid < 128) {
        int d = tid;
        float acc = 0.f;
#pragma unroll
        for (int hh = 0; hh < HB; hh++) acc += sv[hh][d];
        float fin = xin[(size_t)b * DB + d];
        xout[(size_t)b * DB + d] = acc * 0.125f + fin + bias[d];
    }
}

// ---------------- readout ----------------
__global__ void readout_k(const float* __restrict__ x, const int* __restrict__ mask,
                          float* __restrict__ out) {
    int b = blockIdx.x;
    int n = b / LB, l = b % LB;
    int d = threadIdx.x;
    float s = 0.f;
#pragma unroll
    for (int t = 0; t < ATOMS; t++) {
        int a = l * ATOMS + t;
        if (mask[n * AB + a] != 0) s += x[(size_t)(n * AB + a) * DB + d];
    }
    out[(size_t)b * DB + d] = s;
}

// ---------------- launch ----------------
extern "C" void kernel_launch(void* const* d_in, const int* in_sizes, int n_in,
                              void* d_out, int out_size) {
    const float*        feats = (const float*)d_in[0];
    const int*          mask  = (const int*)d_in[1];
    const unsigned int* emask = (const unsigned int*)d_in[2];
    const float*        W     = (const float*)d_in[3];
    const float*        ssrc  = (const float*)d_in[4];
    const float*        stag  = (const float*)d_in[5];
    const float*        bias  = (const float*)d_in[6];
    const float*        lng   = (const float*)d_in[7];
    const float*        lnb   = (const float*)d_in[8];
    float* out = (float*)d_out;

    const int SMEMB = 2 * (64 + 128) * LDSB * 2;   // 104448 bytes
    cudaFuncSetAttribute(gemm_fp_k, cudaFuncAttributeMaxDynamicSharedMemorySize, SMEMB);

    float *px0 = nullptr, *px1 = nullptr;
    cudaGetSymbolAddress((void**)&px0, g_x0);
    cudaGetSymbolAddress((void**)&px1, g_x1);

    pack_edges_k<<<(NB * AB * WORDS) / 8, 256>>>(emask);

    const float* xin = feats;
    float* bufs[2] = {px0, px1};
    for (int l = 0; l < DEPTH; l++) {
        float* xout = bufs[l & 1];
        gemm_fp_k<<<dim3(RB / 64, HB), 256, SMEMB>>>(xin, W + (size_t)l * EB * DB, mask,
                                                     ssrc + l * HB * DB, stag + l * HB * DB);
        attn_k<<<NB * HB * (AB / ATILE), 256>>>();
        epi_k<<<RB, 256>>>(xin, xout, lng + l * DB, lnb + l * DB, bias + l * DB);
        xin = xout;
    }
    readout_k<<<NB * LB, 128>>>(xin, mask, out);
}